// round 4
// baseline (speedup 1.0000x reference)
#include <cuda_runtime.h>
#include <cuda_bf16.h>
#include <cstdint>

#define NN 116736   // nodes = 2048*57
#define NE 327680   // edges = 2048*160
#define MF 163840   // branch rows = 2048*80
#define NL 5
#define HID 256

// ---------------- scratch (device globals; no allocations allowed) ----------
static __device__ float g_h0[(size_t)NN * HID];
static __device__ float g_h1[(size_t)NN * HID];
static __device__ float g_b [(size_t)NN * HID];   // fp32 edge operand b
static __device__ float g_c [(size_t)NN * HID];   // fp32 edge aggregate
static __device__ float g_a [(size_t)MF * HID];   // fp32 edge operand a / final hidden
static __device__ int   g_cnt[NN];
static __device__ float g_deginv[NN];
static __device__ float g_gate[NN];
static __device__ float g_bns[NL * HID];
static __device__ float g_bnt[NL * HID];
static __device__ int   g_uidx[MF];
static __device__ int   g_vidx[MF];

// bf16 hi/lo activation pairs
static __device__ __nv_bfloat16 g_p0h[(size_t)NN * HID], g_p0l[(size_t)NN * HID];
static __device__ __nv_bfloat16 g_p1h[(size_t)NN * HID], g_p1l[(size_t)NN * HID];
static __device__ __nv_bfloat16 g_qh [(size_t)NN * HID], g_ql [(size_t)NN * HID];
static __device__ __nv_bfloat16 g_rh [(size_t)NN * HID], g_rl [(size_t)NN * HID];
static __device__ __nv_bfloat16 g_sh [(size_t)NN * HID], g_sl [(size_t)NN * HID];

// transposed + bf16-split weights: layout [n][K] per matrix, concatenated
#define WT_LSTRIDE 393216
#define WT_MSGD 0
#define WT_MSGS 65536
#define WT_MSG2 131072
#define WT_UPD1 196608
#define WT_UPD2 327680
#define WT_MLP1 1966080
#define WT_TOTAL 2097152
static __device__ __nv_bfloat16 g_wth[WT_TOTAL];
static __device__ __nv_bfloat16 g_wtl[WT_TOTAL];

// ---------------- PTX helpers ------------------------------------------------
__device__ __forceinline__ uint32_t smem_u32(const void* p) {
    uint32_t a;
    asm("{ .reg .u64 t; cvta.to.shared.u64 t, %1; cvt.u32.u64 %0, t; }" : "=r"(a) : "l"(p));
    return a;
}
__device__ __forceinline__ void ldm_x4(uint32_t& r0, uint32_t& r1, uint32_t& r2,
                                       uint32_t& r3, uint32_t addr) {
    asm volatile("ldmatrix.sync.aligned.m8n8.x4.shared.b16 {%0,%1,%2,%3}, [%4];"
                 : "=r"(r0), "=r"(r1), "=r"(r2), "=r"(r3) : "r"(addr));
}
__device__ __forceinline__ void mma_bf16(float* d, const uint32_t* a, const uint32_t* b) {
    asm volatile("mma.sync.aligned.m16n8k16.row.col.f32.bf16.bf16.f32 "
                 "{%0,%1,%2,%3}, {%4,%5,%6,%7}, {%8,%9}, {%0,%1,%2,%3};"
                 : "+f"(d[0]), "+f"(d[1]), "+f"(d[2]), "+f"(d[3])
                 : "r"(a[0]), "r"(a[1]), "r"(a[2]), "r"(a[3]), "r"(b[0]), "r"(b[1]));
}
__device__ __forceinline__ void cp16(uint32_t dst, const void* src) {
    asm volatile("cp.async.ca.shared.global [%0], [%1], 16;" :: "r"(dst), "l"(src));
}
__device__ __forceinline__ void cp_commit() {
    asm volatile("cp.async.commit_group;" ::: "memory");
}
template <int N>
__device__ __forceinline__ void cp_wait() {
    asm volatile("cp.async.wait_group %0;" :: "n"(N) : "memory");
}

// SMEM stage layout: tiles padded to 40-half row stride (conflict-free ldmatrix)
// A: 64 rows x 32 cols (hi 5120 B, lo 5120 B); B: 256 rows x 32 cols (hi/lo 20480 B)
#define ASTG_H 0
#define ASTG_L 5120
#define BSTG_H 10240
#define BSTG_L 30720
#define STAGE  51200
#define SMEM_BYTES 102400

// ---------------- HMMA GEMM: C[M,256] = A@Wt^T (bf16x3 split, fp32 acc) -----
// A supplied as bf16 hi/lo pair. K = 256 (single A) or 512 (chunks 8+ from A2).
// mode: 0 = +bias*gate, 1 = relu(+bias), 2 = BN+relu+residual(+bias)
// Outputs: fp32 C (optional) and/or bf16 pair Ch/Cl (optional).
__global__ __launch_bounds__(256) void gemm_hmma(
    const __nv_bfloat16* __restrict__ A1h, const __nv_bfloat16* __restrict__ A1l,
    const __nv_bfloat16* __restrict__ A2h, const __nv_bfloat16* __restrict__ A2l,
    const int* __restrict__ idx1, const int* __restrict__ idx2,
    const __nv_bfloat16* __restrict__ wh, const __nv_bfloat16* __restrict__ wl, int K,
    const float* __restrict__ bias, const float* __restrict__ biasgate,
    const float* __restrict__ resid,
    const float* __restrict__ bn_s, const float* __restrict__ bn_t,
    float* __restrict__ C, __nv_bfloat16* __restrict__ Ch, __nv_bfloat16* __restrict__ Cl,
    int mode)
{
    extern __shared__ char smem[];
    const uint32_t sb = smem_u32(smem);
    const int tid  = threadIdx.x;
    const int wid  = tid >> 5;
    const int lane = tid & 31;
    const int wm   = wid & 1;        // 2 warps along M: 32 rows each
    const int wn   = wid >> 1;       // 4 warps along N: 64 cols each
    const int row0 = blockIdx.x * 64;
    const int nch  = K >> 5;

    float acc[2][8][4];
    #pragma unroll
    for (int mt = 0; mt < 2; mt++)
        #pragma unroll
        for (int nt = 0; nt < 8; nt++)
            #pragma unroll
            for (int j = 0; j < 4; j++) acc[mt][nt][j] = 0.f;

    // per-lane ldmatrix byte offsets within a stage (proven R3 mapping)
    const uint32_t aoff = ((wm * 32 + (lane & 7) + ((lane >> 3) & 1) * 8) * 40
                           + ((lane >> 4) & 1) * 8) * 2;
    const uint32_t boff = ((wn * 64 + (lane & 7) + ((lane >> 4) & 1) * 8) * 40
                           + ((lane >> 3) & 1) * 8) * 2;

    // ---- issue cp.async for chunk c into stage (c & 1) ----------------------
    auto issue = [&](int c) {
        const int kb = c * 32;
        const __nv_bfloat16 *Ah, *Al;
        const int* idx;
        int kloc;
        if (A2h != nullptr && c >= 8) { Ah = A2h; Al = A2l; idx = idx2; kloc = kb - 256; }
        else                          { Ah = A1h; Al = A1l; idx = idx1; kloc = kb; }
        const uint32_t st = sb + (uint32_t)(c & 1) * STAGE;
        {   // A: 64 rows x 32 cols, one 16B line per thread per half
            int r  = tid >> 2;
            int sg = tid & 3;
            int grow = row0 + r;
            int arow = idx ? idx[grow] : grow;
            size_t s0 = (size_t)arow * 256 + kloc + sg * 8;
            uint32_t d = (uint32_t)(r * 40 + sg * 8) * 2;
            cp16(st + ASTG_H + d, Ah + s0);
            cp16(st + ASTG_L + d, Al + s0);
        }
        #pragma unroll
        for (int i = 0; i < 4; i++) {   // B: 256 rows x 32 cols
            int f = tid + i * 256;
            int n = f >> 2;
            int sg = f & 3;
            size_t s0 = (size_t)n * K + kb + sg * 8;
            uint32_t d = (uint32_t)(n * 40 + sg * 8) * 2;
            cp16(st + BSTG_H + d, wh + s0);
            cp16(st + BSTG_L + d, wl + s0);
        }
        cp_commit();
    };

    // ---- compute chunk c from stage (c & 1) ---------------------------------
    auto compute = [&](int c) {
        const uint32_t base = sb + (uint32_t)(c & 1) * STAGE;
        #pragma unroll
        for (int ks = 0; ks < 2; ks++) {
            uint32_t ah[2][4], al[2][4];
            #pragma unroll
            for (int mt = 0; mt < 2; mt++) {
                uint32_t ad = base + ASTG_H + aoff + mt * 1280 + ks * 32;
                ldm_x4(ah[mt][0], ah[mt][1], ah[mt][2], ah[mt][3], ad);
                ldm_x4(al[mt][0], al[mt][1], al[mt][2], al[mt][3], ad + ASTG_L);
            }
            uint32_t bh[8][2], bl[8][2];
            #pragma unroll
            for (int p = 0; p < 4; p++) {
                uint32_t bd = base + BSTG_H + boff + p * 1280 + ks * 32;
                ldm_x4(bh[2 * p][0], bh[2 * p][1], bh[2 * p + 1][0], bh[2 * p + 1][1], bd);
                ldm_x4(bl[2 * p][0], bl[2 * p][1], bl[2 * p + 1][0], bl[2 * p + 1][1],
                       bd + (BSTG_L - BSTG_H));
            }
            #pragma unroll
            for (int mt = 0; mt < 2; mt++)
                #pragma unroll
                for (int nt = 0; nt < 8; nt++) {
                    mma_bf16(acc[mt][nt], ah[mt], bh[nt]);
                    mma_bf16(acc[mt][nt], ah[mt], bl[nt]);
                    mma_bf16(acc[mt][nt], al[mt], bh[nt]);
                }
        }
    };

    // ---- 2-stage cp.async pipeline ------------------------------------------
    issue(0);
    for (int c = 0; c < nch; c++) {
        if (c + 1 < nch) { issue(c + 1); cp_wait<1>(); }
        else             { cp_wait<0>(); }
        __syncthreads();
        compute(c);
        __syncthreads();
    }

    // ---- epilogue straight from accumulator fragments ------------------------
    const int rw = row0 + wm * 32;
    const int cw = wn * 64;
    #pragma unroll
    for (int mt = 0; mt < 2; mt++) {
        #pragma unroll
        for (int hh = 0; hh < 2; hh++) {
            const int r = rw + mt * 16 + hh * 8 + (lane >> 2);
            const float gate = biasgate ? biasgate[r] : 1.0f;
            #pragma unroll
            for (int nt = 0; nt < 8; nt++) {
                const int cg = cw + nt * 8 + 2 * (lane & 3);
                float vx = acc[mt][nt][hh * 2 + 0];
                float vy = acc[mt][nt][hh * 2 + 1];
                if (bias) { vx += bias[cg] * gate; vy += bias[cg + 1] * gate; }
                if (mode == 1) {
                    vx = fmaxf(vx, 0.f); vy = fmaxf(vy, 0.f);
                } else if (mode == 2) {
                    const float2 rv = *(const float2*)&resid[(size_t)r * 256 + cg];
                    vx = fmaxf(vx * bn_s[cg]     + bn_t[cg],     0.f) + rv.x;
                    vy = fmaxf(vy * bn_s[cg + 1] + bn_t[cg + 1], 0.f) + rv.y;
                }
                if (C) *(float2*)&C[(size_t)r * 256 + cg] = make_float2(vx, vy);
                if (Ch) {
                    __nv_bfloat16 hx = __float2bfloat16(vx);
                    __nv_bfloat16 hy = __float2bfloat16(vy);
                    __nv_bfloat16 lx = __float2bfloat16(vx - __bfloat162float(hx));
                    __nv_bfloat16 ly = __float2bfloat16(vy - __bfloat162float(hy));
                    *(__nv_bfloat162*)&Ch[(size_t)r * 256 + cg] = make_bfloat162(hx, hy);
                    *(__nv_bfloat162*)&Cl[(size_t)r * 256 + cg] = make_bfloat162(lx, ly);
                }
            }
        }
    }
}

// ---------------- weight prep: transpose + bf16 hi/lo split -----------------
__global__ void wprep_kernel(const float* __restrict__ src, int sstride,
                             __nv_bfloat16* __restrict__ wh, __nv_bfloat16* __restrict__ wl,
                             int doff, int K)
{
    int l = blockIdx.y;
    int k = blockIdx.x;
    int n = threadIdx.x;
    float v = src[(size_t)l * sstride + (size_t)k * 256 + n];
    __nv_bfloat16 hb = __float2bfloat16(v);
    __nv_bfloat16 lb = __float2bfloat16(v - __bfloat162float(hb));
    size_t d = (size_t)doff + (size_t)l * WT_LSTRIDE + (size_t)n * K + k;
    wh[d] = hb;
    wl[d] = lb;
}

// ---------------- split: fp32 (x rowscale) -> bf16 hi/lo pair ---------------
__global__ __launch_bounds__(256) void split_kernel(
    const float* __restrict__ src, const float* __restrict__ rowscale,
    __nv_bfloat16* __restrict__ dh, __nv_bfloat16* __restrict__ dl)
{
    size_t i = ((size_t)blockIdx.x * 256 + threadIdx.x) * 4;
    int row = (int)(i >> 8);
    float s = rowscale[row];
    float4 v = *(const float4*)&src[i];
    float vf[4] = {v.x * s, v.y * s, v.z * s, v.w * s};
    __nv_bfloat16 hb[4], lb[4];
    #pragma unroll
    for (int j = 0; j < 4; j++) {
        hb[j] = __float2bfloat16(vf[j]);
        lb[j] = __float2bfloat16(vf[j] - __bfloat162float(hb[j]));
    }
    *(__nv_bfloat162*)&dh[i]     = make_bfloat162(hb[0], hb[1]);
    *(__nv_bfloat162*)&dh[i + 2] = make_bfloat162(hb[2], hb[3]);
    *(__nv_bfloat162*)&dl[i]     = make_bfloat162(lb[0], lb[1]);
    *(__nv_bfloat162*)&dl[i + 2] = make_bfloat162(lb[2], lb[3]);
}

// ---------------- input GEMM: h = x[N,16] @ in_w[16,256] + in_b -------------
__global__ __launch_bounds__(256) void ingemm_kernel(
    const float* __restrict__ x, const float* __restrict__ w,
    const float* __restrict__ bias, float* __restrict__ h,
    __nv_bfloat16* __restrict__ hh, __nv_bfloat16* __restrict__ hl)
{
    __shared__ float ws[16][256];
    __shared__ float xs[32][16];
    int c = threadIdx.x;
    #pragma unroll
    for (int k = 0; k < 16; k++) ws[k][c] = w[k * 256 + c];
    int r0 = blockIdx.x * 32;
    for (int i = threadIdx.x; i < 512; i += 256) xs[i >> 4][i & 15] = x[(size_t)r0 * 16 + i];
    __syncthreads();
    float bb = bias[c];
    for (int r = 0; r < 32; r++) {
        float acc = bb;
        #pragma unroll
        for (int k = 0; k < 16; k++) acc += xs[r][k] * ws[k][c];
        size_t o = (size_t)(r0 + r) * 256 + c;
        h[o] = acc;
        __nv_bfloat16 hb = __float2bfloat16(acc);
        hh[o] = hb;
        hl[o] = __float2bfloat16(acc - __bfloat162float(hb));
    }
}

// ---------------- degree / BN / index precompute ----------------------------
__global__ void count_kernel(const int* __restrict__ ei, int* __restrict__ cnt) {
    int e = blockIdx.x * 256 + threadIdx.x;
    if (e < NE) atomicAdd(&cnt[ei[NE + e]], 1);
}
__global__ void deg_kernel(const int* __restrict__ cnt, float* __restrict__ deginv,
                           float* __restrict__ gate) {
    int n = blockIdx.x * 256 + threadIdx.x;
    if (n < NN) {
        int c = cnt[n];
        deginv[n] = 1.0f / (float)max(c, 1);
        gate[n]   = (c > 0) ? 1.0f : 0.0f;
    }
}
__global__ void bnprep_kernel(const float* __restrict__ g, const float* __restrict__ b,
                              const float* __restrict__ m, const float* __restrict__ v,
                              float* __restrict__ s, float* __restrict__ t) {
    int i = blockIdx.x * 256 + threadIdx.x;
    if (i < NL * HID) {
        float sc = g[i] * rsqrtf(v[i] + 1e-5f);
        s[i] = sc;
        t[i] = b[i] - m[i] * sc;
    }
}
__global__ void idx_kernel(int* __restrict__ u, int* __restrict__ v) {
    int r = blockIdx.x * 256 + threadIdx.x;
    if (r < MF) {
        int g = r / 80, i = r % 80;
        u[r] = g * 57 + (i % 57);
        v[r] = g * 57 + ((i * 13 + 1) % 57);
    }
}

// ---------------- edge phase: scatter relu(a[dst]+b[src]) into agg ----------
__global__ __launch_bounds__(256) void edge_kernel(
    const float* __restrict__ a, const float* __restrict__ b,
    const int* __restrict__ ei, float* __restrict__ agg)
{
    int e = blockIdx.x * 8 + (threadIdx.x >> 5);
    int lane = threadIdx.x & 31;
    int s = ei[e];
    int d = ei[NE + e];
    size_t od = (size_t)d * 256 + lane * 8;
    size_t os = (size_t)s * 256 + lane * 8;
    float4 u0 = *(const float4*)(a + od);
    float4 u1 = *(const float4*)(a + od + 4);
    float4 v0 = *(const float4*)(b + os);
    float4 v1 = *(const float4*)(b + os + 4);
    float h0x = fmaxf(u0.x + v0.x, 0.f), h0y = fmaxf(u0.y + v0.y, 0.f);
    float h0z = fmaxf(u0.z + v0.z, 0.f), h0w = fmaxf(u0.w + v0.w, 0.f);
    float h1x = fmaxf(u1.x + v1.x, 0.f), h1y = fmaxf(u1.y + v1.y, 0.f);
    float h1z = fmaxf(u1.z + v1.z, 0.f), h1w = fmaxf(u1.w + v1.w, 0.f);
    asm volatile("red.global.add.v4.f32 [%0], {%1, %2, %3, %4};"
                 :: "l"(agg + od), "f"(h0x), "f"(h0y), "f"(h0z), "f"(h0w) : "memory");
    asm volatile("red.global.add.v4.f32 [%0], {%1, %2, %3, %4};"
                 :: "l"(agg + od + 4), "f"(h1x), "f"(h1y), "f"(h1z), "f"(h1w) : "memory");
}

// ---------------- final dot: out = hidden_f @ mlp_w2 + mlp_b2 ---------------
__global__ __launch_bounds__(256) void outdot_kernel(
    const float* __restrict__ hf, const float* __restrict__ w2,
    const float* __restrict__ b2, float* __restrict__ out)
{
    int m = blockIdx.x * 8 + (threadIdx.x >> 5);
    int lane = threadIdx.x & 31;
    const float4* hp = (const float4*)(hf + (size_t)m * 256);
    const float4* wp = (const float4*)w2;
    float acc = 0.f;
    #pragma unroll
    for (int i = 0; i < 2; i++) {
        float4 h4 = hp[lane * 2 + i];
        float4 w4 = wp[lane * 2 + i];
        acc += h4.x * w4.x + h4.y * w4.y + h4.z * w4.z + h4.w * w4.w;
    }
    #pragma unroll
    for (int o = 16; o; o >>= 1) acc += __shfl_xor_sync(0xffffffffu, acc, o);
    if (lane == 0) out[m] = acc + b2[0];
}

// ---------------- launcher --------------------------------------------------
extern "C" void kernel_launch(void* const* d_in, const int* in_sizes, int n_in,
                              void* d_out, int out_size)
{
    const float* x      = (const float*)d_in[0];
    const int*   ei     = (const int*)  d_in[1];
    const float* in_w   = (const float*)d_in[3];
    const float* in_b   = (const float*)d_in[4];
    const float* msg_w1 = (const float*)d_in[5];
    const float* msg_b1 = (const float*)d_in[6];
    const float* msg_w2 = (const float*)d_in[7];
    const float* msg_b2 = (const float*)d_in[8];
    const float* upd_w1 = (const float*)d_in[9];
    const float* upd_b1 = (const float*)d_in[10];
    const float* upd_w2 = (const float*)d_in[11];
    const float* upd_b2 = (const float*)d_in[12];
    const float* bn_g   = (const float*)d_in[13];
    const float* bn_b   = (const float*)d_in[14];
    const float* bn_m   = (const float*)d_in[15];
    const float* bn_v   = (const float*)d_in[16];
    const float* mlp_w1 = (const float*)d_in[17];
    const float* mlp_b1 = (const float*)d_in[18];
    const float* mlp_w2 = (const float*)d_in[19];
    const float* mlp_b2 = (const float*)d_in[20];
    float* out = (float*)d_out;

    float *h0, *h1, *ba, *bb, *bc, *deginv, *gate, *bns, *bnt;
    int *cnt, *uix, *vix;
    __nv_bfloat16 *wth, *wtl, *p0h, *p0l, *p1h, *p1l, *qh, *ql, *rh, *rl, *sh, *sl;
    cudaGetSymbolAddress((void**)&h0, g_h0);
    cudaGetSymbolAddress((void**)&h1, g_h1);
    cudaGetSymbolAddress((void**)&bb, g_b);
    cudaGetSymbolAddress((void**)&bc, g_c);
    cudaGetSymbolAddress((void**)&ba, g_a);
    cudaGetSymbolAddress((void**)&cnt, g_cnt);
    cudaGetSymbolAddress((void**)&deginv, g_deginv);
    cudaGetSymbolAddress((void**)&gate, g_gate);
    cudaGetSymbolAddress((void**)&bns, g_bns);
    cudaGetSymbolAddress((void**)&bnt, g_bnt);
    cudaGetSymbolAddress((void**)&uix, g_uidx);
    cudaGetSymbolAddress((void**)&vix, g_vidx);
    cudaGetSymbolAddress((void**)&wth, g_wth);
    cudaGetSymbolAddress((void**)&wtl, g_wtl);
    cudaGetSymbolAddress((void**)&p0h, g_p0h);
    cudaGetSymbolAddress((void**)&p0l, g_p0l);
    cudaGetSymbolAddress((void**)&p1h, g_p1h);
    cudaGetSymbolAddress((void**)&p1l, g_p1l);
    cudaGetSymbolAddress((void**)&qh, g_qh);
    cudaGetSymbolAddress((void**)&ql, g_ql);
    cudaGetSymbolAddress((void**)&rh, g_rh);
    cudaGetSymbolAddress((void**)&rl, g_rl);
    cudaGetSymbolAddress((void**)&sh, g_sh);
    cudaGetSymbolAddress((void**)&sl, g_sl);

    cudaFuncSetAttribute(gemm_hmma, cudaFuncAttributeMaxDynamicSharedMemorySize, SMEM_BYTES);

    cudaMemsetAsync(cnt, 0, NN * sizeof(int), 0);
    count_kernel<<<NE / 256, 256>>>(ei, cnt);
    deg_kernel<<<NN / 256, 256>>>(cnt, deginv, gate);
    bnprep_kernel<<<NL, 256>>>(bn_g, bn_b, bn_m, bn_v, bns, bnt);
    idx_kernel<<<MF / 256, 256>>>(uix, vix);

    // weight prep (transpose + bf16 hi/lo split)
    wprep_kernel<<<dim3(256, NL), 256>>>(msg_w1,               131072, wth, wtl, WT_MSGD, 256);
    wprep_kernel<<<dim3(256, NL), 256>>>(msg_w1 + 256 * 256,   131072, wth, wtl, WT_MSGS, 256);
    wprep_kernel<<<dim3(256, NL), 256>>>(msg_w2,                65536, wth, wtl, WT_MSG2, 256);
    wprep_kernel<<<dim3(512, NL), 256>>>(upd_w1,               131072, wth, wtl, WT_UPD1, 512);
    wprep_kernel<<<dim3(256, NL), 256>>>(upd_w2,                65536, wth, wtl, WT_UPD2, 256);
    wprep_kernel<<<dim3(512, 1),  256>>>(mlp_w1,                    0, wth, wtl, WT_MLP1, 512);

    ingemm_kernel<<<NN / 32, 256>>>(x, in_w, in_b, h0, p0h, p0l);

    const int gN = NN / 64;   // 1824
    for (int l = 0; l < NL; l++) {
        float* hc = (l & 1) ? h1 : h0;
        float* hn = (l & 1) ? h0 : h1;
        __nv_bfloat16* pch = (l & 1) ? p1h : p0h;
        __nv_bfloat16* pcl = (l & 1) ? p1l : p0l;
        __nv_bfloat16* pnh = (l & 1) ? p0h : p1h;
        __nv_bfloat16* pnl = (l & 1) ? p0l : p1l;
        size_t lw = (size_t)l * WT_LSTRIDE;

        // a = h @ Wdst^T + msg_b1  (fp32 out for edge phase)
        gemm_hmma<<<gN, 256, SMEM_BYTES>>>(pch, pcl, nullptr, nullptr, nullptr, nullptr,
            wth + lw + WT_MSGD, wtl + lw + WT_MSGD, 256,
            msg_b1 + l * 256, nullptr, nullptr, nullptr, nullptr,
            ba, nullptr, nullptr, 0);
        // b = h @ Wsrc^T
        gemm_hmma<<<gN, 256, SMEM_BYTES>>>(pch, pcl, nullptr, nullptr, nullptr, nullptr,
            wth + lw + WT_MSGS, wtl + lw + WT_MSGS, 256,
            nullptr, nullptr, nullptr, nullptr, nullptr,
            bb, nullptr, nullptr, 0);
        // aggH = scatter_add relu(a[dst] + b[src])
        cudaMemsetAsync(bc, 0, (size_t)NN * 256 * sizeof(float), 0);
        edge_kernel<<<NE / 8, 256>>>(ba, bb, ei, bc);
        // q = (aggH / deg) as bf16 pair
        split_kernel<<<NN * 256 / 1024, 256>>>(bc, deginv, qh, ql);
        // aggm = q @ W2^T + gate*b2  (bf16 pair out)
        gemm_hmma<<<gN, 256, SMEM_BYTES>>>(qh, ql, nullptr, nullptr, nullptr, nullptr,
            wth + lw + WT_MSG2, wtl + lw + WT_MSG2, 256,
            msg_b2 + l * 256, gate, nullptr, nullptr, nullptr,
            nullptr, rh, rl, 0);
        // t = relu(h @ Utop^T + aggm @ Ubot^T + upd_b1)  (bf16 pair out)
        gemm_hmma<<<gN, 256, SMEM_BYTES>>>(pch, pcl, rh, rl, nullptr, nullptr,
            wth + lw + WT_UPD1, wtl + lw + WT_UPD1, 512,
            upd_b1 + l * 256, nullptr, nullptr, nullptr, nullptr,
            nullptr, sh, sl, 1);
        // h' = relu(BN(t @ U2^T + upd_b2)) + h  (fp32 + bf16 pair out)
        gemm_hmma<<<gN, 256, SMEM_BYTES>>>(sh, sl, nullptr, nullptr, nullptr, nullptr,
            wth + lw + WT_UPD2, wtl + lw + WT_UPD2, 256,
            upd_b2 + l * 256, nullptr, hc, bns + l * 256, bnt + l * 256,
            hn, pnh, pnl, 2);
    }

    // final pair after 5 layers = p1
    gemm_hmma<<<MF / 64, 256, SMEM_BYTES>>>(p1h, p1l, p1h, p1l, uix, vix,
        wth + WT_MLP1, wtl + WT_MLP1, 512,
        mlp_b1, nullptr, nullptr, nullptr, nullptr,
        ba, nullptr, nullptr, 1);
    outdot_kernel<<<MF / 8, 256>>>(ba, mlp_w2, mlp_b2, out);
}